// round 1
// baseline (speedup 1.0000x reference)
#include <cuda_runtime.h>
#include <math.h>

// SPUPointwise: per-element sound linear bounds for SPU(x) = x^2-0.5 (x>=0),
// sigmoid(-x)-1 (x<0), backsubstituted against constant input bounds [l,u].
// Pure pointwise, HBM-bound. One fused pass, float4 vectorized.
//
// Output layout: out[0..N)   = nl
//                out[N..2N)  = nu
// (reference returns tuple (nl, nu); harness flattens in order)

__device__ __forceinline__ float spu_f(float x) {
    if (x >= 0.0f) return fmaf(x, x, -0.5f);
    // sigmoid(-x) - 1 = 1/(1+e^x) - 1
    float t = expf(x);
    return 1.0f / (1.0f + t) - 1.0f;
}

__device__ __forceinline__ float spu_grad_f(float x) {
    if (x >= 0.0f) return 2.0f * x;
    if (x <= -50.0f) return 0.0f;
    return -0.5f / (coshf(x) + 1.0f);
}

__device__ __forceinline__ void spu_bounds(float l, float u, float& nl, float& nu) {
    const float sl = spu_f(l);
    const float su = spu_f(u);

    // chord (l,sl)-(u,su)
    const float a_lu = (su - sl) / (u - l + 1e-8f);
    const float b_lu = sl - l * a_lu;

    // tangent at midpoint
    const float mid = 0.5f * (l + u);
    const float a_t = spu_grad_f(mid);
    const float b_t = spu_f(mid) - a_t * mid;

    const bool neg = (u < 0.0f);
    const bool pos = (!neg) && (l > 0.0f);

    float lw, lb, uw, ub;
    if (neg) {
        lw = a_lu; lb = b_lu; uw = a_t; ub = b_t;
    } else if (pos) {
        lw = a_t;  lb = b_t;  uw = a_lu; ub = b_lu;
    } else {
        // mixed: l <= 0 <= u
        const bool normal = (su > sl);   // spu_mixed_normal_u

        // candidate 1: chord from (l, sl) to (0, -0.5)
        const float a1 = (-0.5f - sl) / (-l + 1e-8f);
        const float b1 = sl - l * a1;
        // candidate 2: tangent at h = u/2 (h >= 0 here, so quadratic branch)
        const float h  = 0.5f * u;
        const float a2 = 2.0f * h;                       // spu_grad(h), h>=0
        const float b2 = fmaf(h, h, -0.5f) - a2 * h;     // spu(h) - a2*h

        // area proxy: -(u-l)*(a*(l+u) + 2b)
        const float s   = -(u - l);
        const float lu  = l + u;
        const float ar0 = s * (-1.0f);                   // a=0, b=-0.5
        const float ar1 = s * (a1 * lu + 2.0f * b1);
        const float ar2 = normal ? s * (a2 * lu + 2.0f * b2) : INFINITY;

        // first-min argmin over [ar0, ar1, ar2]
        int idx = 0; float best = ar0;
        if (ar1 < best) { best = ar1; idx = 1; }
        if (ar2 < best) { idx = 2; }

        lw = (idx == 0) ? 0.0f  : ((idx == 1) ? a1 : a2);
        lb = (idx == 0) ? -0.5f : ((idx == 1) ? b1 : b2);
        uw = normal ? a_lu : 0.0f;
        ub = normal ? b_lu : sl;
    }

    nl = lb + (lw > 0.0f ? lw * l : lw * u);
    nu = ub + (uw > 0.0f ? uw * u : uw * l);
}

__global__ void __launch_bounds__(256)
spu_pointwise_kernel(const float4* __restrict__ l4,
                     const float4* __restrict__ u4,
                     float4* __restrict__ nl4,
                     float4* __restrict__ nu4,
                     int n4) {
    int i = blockIdx.x * blockDim.x + threadIdx.x;
    if (i >= n4) return;

    const float4 lv = l4[i];
    const float4 uv = u4[i];
    float4 nlv, nuv;
    spu_bounds(lv.x, uv.x, nlv.x, nuv.x);
    spu_bounds(lv.y, uv.y, nlv.y, nuv.y);
    spu_bounds(lv.z, uv.z, nlv.z, nuv.z);
    spu_bounds(lv.w, uv.w, nlv.w, nuv.w);
    nl4[i] = nlv;
    nu4[i] = nuv;
}

// scalar tail (n not divisible by 4) — not expected for 64*65536 but kept safe
__global__ void spu_pointwise_tail(const float* __restrict__ l,
                                   const float* __restrict__ u,
                                   float* __restrict__ nl,
                                   float* __restrict__ nu,
                                   int start, int n) {
    int i = start + blockIdx.x * blockDim.x + threadIdx.x;
    if (i >= n) return;
    spu_bounds(l[i], u[i], nl[i], nu[i]);
}

extern "C" void kernel_launch(void* const* d_in, const int* in_sizes, int n_in,
                              void* d_out, int out_size) {
    const float* l = (const float*)d_in[0];
    const float* u = (const float*)d_in[1];
    float* out = (float*)d_out;
    const int n = in_sizes[0];
    float* nl = out;
    float* nu = out + n;

    const int n4 = n >> 2;
    if (n4 > 0) {
        const int threads = 256;
        const int blocks = (n4 + threads - 1) / threads;
        spu_pointwise_kernel<<<blocks, threads>>>(
            (const float4*)l, (const float4*)u,
            (float4*)nl, (float4*)nu, n4);
    }
    const int rem_start = n4 << 2;
    if (rem_start < n) {
        const int rem = n - rem_start;
        spu_pointwise_tail<<<(rem + 255) / 256, 256>>>(l, u, nl, nu, rem_start, n);
    }
}

// round 2
// speedup vs baseline: 1.3011x; 1.3011x over previous
#include <cuda_runtime.h>
#include <math.h>

// SPUPointwise: per-element sound linear bounds for SPU(x) = x^2-0.5 (x>=0),
// sigmoid(-x)-1 (x<0), backsubstituted against constant input bounds [l,u].
//
// R1 -> R2: issue-bound (issue=86.8%, dram=12.8%). Replace accurate libm
// expf/coshf/fdiv with __expf / __frcp_rn / __fdividef and fuse:
//   sigmoid(-x)-1 = -t/(1+t),  -0.5/(cosh(x)+1) = -t/(1+t)^2,  t = e^x
// so spu(x<0) and spu_grad(x<0) share one EX2 + one RCP.
//
// Output layout: out[0..N) = nl, out[N..2N) = nu.

// spu value only
__device__ __forceinline__ float spu_f(float x) {
    if (x >= 0.0f) return fmaf(x, x, -0.5f);
    const float t   = __expf(x);
    const float inv = __frcp_rn(1.0f + t);
    return -t * inv;                       // sigmoid(-x) - 1
}

// spu value + grad at same point (shares t, inv)
__device__ __forceinline__ void spu_vg(float x, float& v, float& g) {
    if (x >= 0.0f) {
        v = fmaf(x, x, -0.5f);
        g = 2.0f * x;
    } else {
        const float t   = __expf(x);
        const float inv = __frcp_rn(1.0f + t);
        v = -t * inv;
        g = (x <= -50.0f) ? 0.0f : (-t * inv) * inv;   // -t/(1+t)^2
    }
}

__device__ __forceinline__ void spu_bounds(float l, float u, float& nl, float& nu) {
    const float sl = spu_f(l);
    const float su = spu_f(u);

    // chord (l,sl)-(u,su)
    const float a_lu = __fdividef(su - sl, u - l + 1e-8f);
    const float b_lu = sl - l * a_lu;

    // tangent at midpoint
    const float mid = 0.5f * (l + u);
    float smid, a_t;
    spu_vg(mid, smid, a_t);
    const float b_t = smid - a_t * mid;

    const bool neg = (u < 0.0f);
    const bool pos = (!neg) && (l > 0.0f);

    float lw, lb, uw, ub;
    if (neg) {
        lw = a_lu; lb = b_lu; uw = a_t; ub = b_t;
    } else if (pos) {
        lw = a_t;  lb = b_t;  uw = a_lu; ub = b_lu;
    } else {
        // mixed: l <= 0 <= u
        const bool normal = (su > sl);   // spu_mixed_normal_u

        // candidate 1: chord from (l, sl) to (0, -0.5)
        const float a1 = __fdividef(-0.5f - sl, -l + 1e-8f);
        const float b1 = sl - l * a1;
        // candidate 2: tangent at h = u/2 (h >= 0 -> quadratic branch)
        const float h  = 0.5f * u;
        const float a2 = 2.0f * h;
        const float b2 = fmaf(h, h, -0.5f) - a2 * h;

        // area proxy: -(u-l)*(a*(l+u) + 2b)
        const float s   = -(u - l);
        const float lu  = l + u;
        const float ar0 = -s;                              // a=0, b=-0.5
        const float ar1 = s * fmaf(a1, lu, 2.0f * b1);
        const float ar2 = normal ? s * fmaf(a2, lu, 2.0f * b2) : INFINITY;

        // first-min argmin over [ar0, ar1, ar2]
        int idx = 0; float best = ar0;
        if (ar1 < best) { best = ar1; idx = 1; }
        if (ar2 < best) { idx = 2; }

        lw = (idx == 0) ? 0.0f  : ((idx == 1) ? a1 : a2);
        lb = (idx == 0) ? -0.5f : ((idx == 1) ? b1 : b2);
        uw = normal ? a_lu : 0.0f;
        ub = normal ? b_lu : sl;
    }

    nl = lb + (lw > 0.0f ? lw * l : lw * u);
    nu = ub + (uw > 0.0f ? uw * u : uw * l);
}

__global__ void __launch_bounds__(256)
spu_pointwise_kernel(const float4* __restrict__ l4,
                     const float4* __restrict__ u4,
                     float4* __restrict__ nl4,
                     float4* __restrict__ nu4,
                     int n4) {
    int i = blockIdx.x * blockDim.x + threadIdx.x;
    if (i >= n4) return;

    const float4 lv = l4[i];
    const float4 uv = u4[i];
    float4 nlv, nuv;
    spu_bounds(lv.x, uv.x, nlv.x, nuv.x);
    spu_bounds(lv.y, uv.y, nlv.y, nuv.y);
    spu_bounds(lv.z, uv.z, nlv.z, nuv.z);
    spu_bounds(lv.w, uv.w, nlv.w, nuv.w);
    nl4[i] = nlv;
    nu4[i] = nuv;
}

// scalar tail (n not divisible by 4)
__global__ void spu_pointwise_tail(const float* __restrict__ l,
                                   const float* __restrict__ u,
                                   float* __restrict__ nl,
                                   float* __restrict__ nu,
                                   int start, int n) {
    int i = start + blockIdx.x * blockDim.x + threadIdx.x;
    if (i >= n) return;
    spu_bounds(l[i], u[i], nl[i], nu[i]);
}

extern "C" void kernel_launch(void* const* d_in, const int* in_sizes, int n_in,
                              void* d_out, int out_size) {
    const float* l = (const float*)d_in[0];
    const float* u = (const float*)d_in[1];
    float* out = (float*)d_out;
    const int n = in_sizes[0];
    float* nl = out;
    float* nu = out + n;

    const int n4 = n >> 2;
    if (n4 > 0) {
        const int threads = 256;
        const int blocks = (n4 + threads - 1) / threads;
        spu_pointwise_kernel<<<blocks, threads>>>(
            (const float4*)l, (const float4*)u,
            (float4*)nl, (float4*)nu, n4);
    }
    const int rem_start = n4 << 2;
    if (rem_start < n) {
        const int rem = n - rem_start;
        spu_pointwise_tail<<<(rem + 255) / 256, 256>>>(l, u, nl, nu, rem_start, n);
    }
}

// round 3
// speedup vs baseline: 2.0000x; 1.5371x over previous
#include <cuda_runtime.h>
#include <math.h>

// SPUPointwise — R3: slim the SASS. Previous round ~170 instrs/element
// (issue=84.9%, dram=16.7%). Changes:
//  * spu(x<0) = -sigmoid(x); grad = s^2 - s  -> one ex2 + one rcp gives both
//  * raw rcp.approx / ex2.approx (no Newton fixups from __frcp_rn)
//  * argmin(area) == first-argmax of q_i = a_i*(l+u)+2*b_i   (since -(u-l)<0)
//    q0 = -1, q2 = u*(l+u/2)-1, b2 = -u^2/4-0.5, pos tangent b_t = -mid^2-0.5
//  * dropped x<=-50 clamp (sigmoid underflow makes it exact enough)
//
// Output layout: out[0..N) = nl, out[N..2N) = nu.

__device__ __forceinline__ float rcpa(float x) {
    float r; asm("rcp.approx.ftz.f32 %0, %1;" : "=f"(r) : "f"(x)); return r;
}
__device__ __forceinline__ float ex2a(float x) {
    float r; asm("ex2.approx.ftz.f32 %0, %1;" : "=f"(r) : "f"(x)); return r;
}
// sigmoid(x) = 1/(1+e^{-x});  e^{-x} = 2^{-x*log2(e)}
__device__ __forceinline__ float sigm(float x) {
    const float e = ex2a(x * -1.44269504088896340736f);
    return rcpa(1.0f + e);
}

__device__ __forceinline__ void spu_bounds(float l, float u, float& nl, float& nu) {
    const bool lneg = (l < 0.0f);
    const bool uneg = (u < 0.0f);

    // spu at endpoints
    const float s_l = sigm(l);
    const float sl  = lneg ? -s_l : fmaf(l, l, -0.5f);
    const float s_u = sigm(u);
    const float su  = uneg ? -s_u : fmaf(u, u, -0.5f);

    // chord (l,sl)-(u,su)
    const float a_lu = (su - sl) * rcpa(u - l + 1e-8f);
    const float b_lu = fmaf(-l, a_lu, sl);

    const float mid = 0.5f * (l + u);

    float lw, lb, uw, ub;
    if (uneg) {
        // ---- neg: lower = chord, upper = tangent at mid (<0) ----
        const float s_m = sigm(mid);
        const float a_t = fmaf(s_m, s_m, -s_m);   // s^2 - s  ( = -s(1-s) )
        const float b_t = fmaf(-a_t, mid, -s_m);  // spu(mid) - a_t*mid
        lw = a_lu; lb = b_lu; uw = a_t; ub = b_t;
    } else if (l > 0.0f) {
        // ---- pos: lower = tangent at mid (>0, quadratic), upper = chord ----
        const float a_t = l + u;                  // 2*mid
        const float b_t = fmaf(-mid, mid, -0.5f); // -(mid^2 + 0.5)
        lw = a_t; lb = b_t; uw = a_lu; ub = b_lu;
    } else {
        // ---- mixed: l <= 0 <= u ----
        const bool normal = (su > sl);

        // candidate 1: chord (l,sl)-(0,-0.5)
        const float a1 = (-0.5f - sl) * rcpa(1e-8f - l);
        const float b1 = fmaf(-l, a1, sl);

        // first-argmax of q_i = a_i*(l+u) + 2*b_i  (== first-argmin of area)
        const float lpu = l + u;
        const float q1  = fmaf(a1, lpu, 2.0f * b1);
        const float q2  = normal ? fmaf(u, fmaf(0.5f, u, l), -1.0f) : -INFINITY;

        float qb = -1.0f;                         // q0
        lw = 0.0f; lb = -0.5f;
        if (q1 > qb) { qb = q1; lw = a1; lb = b1; }
        if (q2 > qb) { lw = u; lb = fmaf(-0.25f * u, u, -0.5f); }

        uw = normal ? a_lu : 0.0f;
        ub = normal ? b_lu : sl;
    }

    // backsubstitution against constant bounds
    nl = fmaf(lw, (lw > 0.0f ? l : u), lb);
    nu = fmaf(uw, (uw > 0.0f ? u : l), ub);
}

__global__ void __launch_bounds__(256)
spu_pointwise_kernel(const float4* __restrict__ l4,
                     const float4* __restrict__ u4,
                     float4* __restrict__ nl4,
                     float4* __restrict__ nu4,
                     int n4) {
    int i = blockIdx.x * blockDim.x + threadIdx.x;
    if (i >= n4) return;

    const float4 lv = l4[i];
    const float4 uv = u4[i];
    float4 nlv, nuv;
    spu_bounds(lv.x, uv.x, nlv.x, nuv.x);
    spu_bounds(lv.y, uv.y, nlv.y, nuv.y);
    spu_bounds(lv.z, uv.z, nlv.z, nuv.z);
    spu_bounds(lv.w, uv.w, nlv.w, nuv.w);
    nl4[i] = nlv;
    nu4[i] = nuv;
}

// scalar tail (n not divisible by 4)
__global__ void spu_pointwise_tail(const float* __restrict__ l,
                                   const float* __restrict__ u,
                                   float* __restrict__ nl,
                                   float* __restrict__ nu,
                                   int start, int n) {
    int i = start + blockIdx.x * blockDim.x + threadIdx.x;
    if (i >= n) return;
    spu_bounds(l[i], u[i], nl[i], nu[i]);
}

extern "C" void kernel_launch(void* const* d_in, const int* in_sizes, int n_in,
                              void* d_out, int out_size) {
    const float* l = (const float*)d_in[0];
    const float* u = (const float*)d_in[1];
    float* out = (float*)d_out;
    const int n = in_sizes[0];
    float* nl = out;
    float* nu = out + n;

    const int n4 = n >> 2;
    if (n4 > 0) {
        const int threads = 256;
        const int blocks = (n4 + threads - 1) / threads;
        spu_pointwise_kernel<<<blocks, threads>>>(
            (const float4*)l, (const float4*)u,
            (float4*)nl, (float4*)nu, n4);
    }
    const int rem_start = n4 << 2;
    if (rem_start < n) {
        const int rem = n - rem_start;
        spu_pointwise_tail<<<(rem + 255) / 256, 256>>>(l, u, nl, nu, rem_start, n);
    }
}

// round 6
// speedup vs baseline: 2.2407x; 1.1204x over previous
#include <cuda_runtime.h>
#include <math.h>

// SPUPointwise — R6 (second resubmit of the branchless kernel; rounds 4 and 5
// both died on "GB300 container failed twice" before compile/run — infra, not
// kernel). Theory unchanged from R4:
//
// R3 measured issue-bound (issue=77.3%, dram=27.2%, ~96 instrs/elem vs ~50
// essential): the 3-way class split compiled to BSSY/BSYNC divergent regions
// that every warp executed serially on random sign data. This version computes
// all three classes straight-line and merges with FSEL selects (zero branch
// machinery). Costs one extra unconditional sigmoid — MUFU budget stays below
// the ~10us memory floor. Mixed-case area-argmin tie-break preserved exactly
// (first-argmin == q1>q0, then q2 strictly > max(q0,q1)).
//
// Output layout: out[0..N) = nl, out[N..2N) = nu.

__device__ __forceinline__ float rcpa(float x) {
    float r; asm("rcp.approx.ftz.f32 %0, %1;" : "=f"(r) : "f"(x)); return r;
}
__device__ __forceinline__ float ex2a(float x) {
    float r; asm("ex2.approx.ftz.f32 %0, %1;" : "=f"(r) : "f"(x)); return r;
}

__device__ __forceinline__ void spu_bounds(float l, float u, float& nl, float& nu) {
    const float NLOG2E = -1.44269504088896340736f;

    // sigmoids at l, u, mid (unconditional; selects pick what's needed)
    const float lpu = l + u;
    const float mid = 0.5f * lpu;
    const float s_l = rcpa(1.0f + ex2a(NLOG2E * l));
    const float s_u = rcpa(1.0f + ex2a(NLOG2E * u));
    const float s_m = rcpa(1.0f + ex2a(NLOG2E * mid));

    // spu at endpoints
    const float sl = (l < 0.0f) ? -s_l : fmaf(l, l, -0.5f);
    const float su = (u < 0.0f) ? -s_u : fmaf(u, u, -0.5f);

    // chord (l,sl)-(u,su)
    const float a_lu = (su - sl) * rcpa(u - l + 1e-8f);
    const float b_lu = fmaf(-l, a_lu, sl);

    // tangent at mid, negative branch: grad = s^2 - s, spu = -s
    const float a_tn = fmaf(s_m, s_m, -s_m);
    const float b_tn = fmaf(-a_tn, mid, -s_m);
    // tangent at mid, positive branch: grad = 2*mid, b = -(mid^2+0.5)
    const float a_tp = lpu;
    const float b_tp = fmaf(-mid, mid, -0.5f);

    // ---- mixed-class lower candidates (valid arithmetic for all inputs) ----
    // c1: chord (l,sl)-(0,-0.5)
    const float a1 = (-0.5f - sl) * rcpa(1e-8f - l);
    const float b1 = fmaf(-l, a1, sl);
    // first-argmax of q_i = a_i*(l+u) + 2*b_i  (== first-argmin of area proxy)
    const float q1 = fmaf(a1, lpu, b1 + b1);
    const bool  normal = (su > sl);
    const float q2 = normal ? fmaf(u, fmaf(0.5f, u, l), -1.0f) : -INFINITY;

    const bool c1 = (q1 > -1.0f);                 // q0 = -1
    float lw_m = c1 ? a1 : 0.0f;
    float lb_m = c1 ? b1 : -0.5f;
    const bool c2 = (q2 > fmaxf(q1, -1.0f));      // strictly beats both
    lw_m = c2 ? u : lw_m;
    lb_m = c2 ? fmaf(-0.25f * u, u, -0.5f) : lb_m;

    const float uw_m = normal ? a_lu : 0.0f;
    const float ub_m = normal ? b_lu : sl;

    // ---- class merge ----
    const bool neg = (u < 0.0f);
    const bool pos = (!neg) && (l > 0.0f);

    const float lw = neg ? a_lu : (pos ? a_tp : lw_m);
    const float lb = neg ? b_lu : (pos ? b_tp : lb_m);
    const float uw = neg ? a_tn : (pos ? a_lu : uw_m);
    const float ub = neg ? b_tn : (pos ? b_lu : ub_m);

    // backsubstitution against constant bounds
    nl = fmaf(lw, (lw > 0.0f) ? l : u, lb);
    nu = fmaf(uw, (uw > 0.0f) ? u : l, ub);
}

__global__ void __launch_bounds__(256)
spu_pointwise_kernel(const float4* __restrict__ l4,
                     const float4* __restrict__ u4,
                     float4* __restrict__ nl4,
                     float4* __restrict__ nu4,
                     int n4) {
    int i = blockIdx.x * blockDim.x + threadIdx.x;
    if (i >= n4) return;

    const float4 lv = l4[i];
    const float4 uv = u4[i];
    float4 nlv, nuv;
    spu_bounds(lv.x, uv.x, nlv.x, nuv.x);
    spu_bounds(lv.y, uv.y, nlv.y, nuv.y);
    spu_bounds(lv.z, uv.z, nlv.z, nuv.z);
    spu_bounds(lv.w, uv.w, nlv.w, nuv.w);
    nl4[i] = nlv;
    nu4[i] = nuv;
}

// scalar tail (n not divisible by 4)
__global__ void __launch_bounds__(256)
spu_pointwise_tail(const float* __restrict__ l,
                   const float* __restrict__ u,
                   float* __restrict__ nl,
                   float* __restrict__ nu,
                   int start, int n) {
    int i = start + blockIdx.x * blockDim.x + threadIdx.x;
    if (i >= n) return;
    spu_bounds(l[i], u[i], nl[i], nu[i]);
}

extern "C" void kernel_launch(void* const* d_in, const int* in_sizes, int n_in,
                              void* d_out, int out_size) {
    const float* l = (const float*)d_in[0];
    const float* u = (const float*)d_in[1];
    float* out = (float*)d_out;
    const int n = in_sizes[0];
    float* nl = out;
    float* nu = out + n;

    const int n4 = n >> 2;
    if (n4 > 0) {
        const int threads = 256;
        const int blocks = (n4 + threads - 1) / threads;
        spu_pointwise_kernel<<<blocks, threads>>>(
            (const float4*)l, (const float4*)u,
            (float4*)nl, (float4*)nu, n4);
    }
    const int rem_start = n4 << 2;
    if (rem_start < n) {
        const int rem = n - rem_start;
        spu_pointwise_tail<<<(rem + 255) / 256, 256>>>(l, u, nl, nu, rem_start, n);
    }
}

// round 9
// speedup vs baseline: 2.2555x; 1.0066x over previous
#include <cuda_runtime.h>
#include <math.h>

// SPUPointwise — R9 (second resubmit of R7; rounds 7 and 8 both died on
// "GB300 container failed twice" before compile/run — same infra flake that
// hit rounds 4/5 before the identical kernel passed at round 6). Theory
// unchanged, from the R6 profile (issue=72.8%, alu=36.9%, fma=26.8%,
// dram=29.3%, no pipe saturated -> mixed instr-count + latency bound):
//  1) MUFU 8->6/elem: one rcp over the product of the 3 sigmoid denominators
//     (all >=1, product <= ~1e22, no zero/overflow risk), recover each via muls.
//  2) Upper-bound merge collapsed: pos-class always has su>sl (monotone
//     quadratic), so uw/ub = neg ? tangent : (su>sl ? chord : (0,sl)).
//  3) 8 elems/thread (2 coalesced float4 chunks) for 2 independent chains to
//     hide MUFU(lat16)/LDG latency and amortize index math.
//
// Output layout: out[0..N) = nl, out[N..2N) = nu.

__device__ __forceinline__ float rcpa(float x) {
    float r; asm("rcp.approx.ftz.f32 %0, %1;" : "=f"(r) : "f"(x)); return r;
}
__device__ __forceinline__ float ex2a(float x) {
    float r; asm("ex2.approx.ftz.f32 %0, %1;" : "=f"(r) : "f"(x)); return r;
}

__device__ __forceinline__ void spu_bounds(float l, float u, float& nl, float& nu) {
    const float NLOG2E = -1.44269504088896340736f;

    const float lpu = l + u;
    const float mid = 0.5f * lpu;

    // three sigmoids with ONE rcp: s_x = 1/(1+e^{-x})
    const float dl = 1.0f + ex2a(NLOG2E * l);
    const float du = 1.0f + ex2a(NLOG2E * u);
    const float dm = 1.0f + ex2a(NLOG2E * mid);
    const float dlu = dl * du;
    const float r3  = rcpa(dlu * dm);
    const float s_l = (du * dm) * r3;
    const float s_u = (dl * dm) * r3;
    const float s_m = dlu * r3;

    // spu at endpoints
    const float sl = (l < 0.0f) ? -s_l : fmaf(l, l, -0.5f);
    const float su = (u < 0.0f) ? -s_u : fmaf(u, u, -0.5f);

    // chord (l,sl)-(u,su)
    const float a_lu = (su - sl) * rcpa(u - l + 1e-8f);
    const float b_lu = fmaf(-l, a_lu, sl);

    // tangent at mid, negative branch: grad = s^2 - s, spu = -s
    const float a_tn = fmaf(s_m, s_m, -s_m);
    const float b_tn = fmaf(-a_tn, mid, -s_m);
    // tangent at mid, positive branch: grad = 2*mid, b = -(mid^2+0.5)
    const float a_tp = lpu;
    const float b_tp = fmaf(-mid, mid, -0.5f);

    // ---- mixed-class lower candidates ----
    // c1: chord (l,sl)-(0,-0.5)
    const float a1 = (-0.5f - sl) * rcpa(1e-8f - l);
    const float b1 = fmaf(-l, a1, sl);
    // first-argmax of q_i = a_i*(l+u)+2*b_i  (== first-argmin of area proxy)
    const float q1 = fmaf(a1, lpu, b1 + b1);
    const bool  tu = (su > sl);   // "normal"; also always true for pos class
    const float q2 = tu ? fmaf(u, fmaf(0.5f, u, l), -1.0f) : -INFINITY;

    const bool c1 = (q1 > -1.0f);                 // q0 = -1
    float lw_m = c1 ? a1 : 0.0f;
    float lb_m = c1 ? b1 : -0.5f;
    const bool c2 = (q2 > fmaxf(q1, -1.0f));
    lw_m = c2 ? u : lw_m;
    lb_m = c2 ? fmaf(-0.25f * u, u, -0.5f) : lb_m;

    // ---- class merge ----
    const bool neg = (u < 0.0f);
    const bool pos = (!neg) && (l > 0.0f);

    const float lw = neg ? a_lu : (pos ? a_tp : lw_m);
    const float lb = neg ? b_lu : (pos ? b_tp : lb_m);
    const float uw = neg ? a_tn : (tu ? a_lu : 0.0f);
    const float ub = neg ? b_tn : (tu ? b_lu : sl);

    // backsubstitution against constant bounds
    nl = fmaf(lw, (lw > 0.0f) ? l : u, lb);
    nu = fmaf(uw, (uw > 0.0f) ? u : l, ub);
}

__device__ __forceinline__ void do4(const float4 lv, const float4 uv,
                                    float4& nlv, float4& nuv) {
    spu_bounds(lv.x, uv.x, nlv.x, nuv.x);
    spu_bounds(lv.y, uv.y, nlv.y, nuv.y);
    spu_bounds(lv.z, uv.z, nlv.z, nuv.z);
    spu_bounds(lv.w, uv.w, nlv.w, nuv.w);
}

__global__ void __launch_bounds__(256)
spu_pointwise_kernel(const float4* __restrict__ l4,
                     const float4* __restrict__ u4,
                     float4* __restrict__ nl4,
                     float4* __restrict__ nu4,
                     int n4) {
    const int i0 = blockIdx.x * 512 + threadIdx.x;   // chunk 0
    const int i1 = i0 + 256;                          // chunk 1

    if (i1 < n4) {
        // both chunks in range: two independent chains
        const float4 lv0 = l4[i0], uv0 = u4[i0];
        const float4 lv1 = l4[i1], uv1 = u4[i1];
        float4 nl0, nu0, nl1, nu1;
        do4(lv0, uv0, nl0, nu0);
        do4(lv1, uv1, nl1, nu1);
        nl4[i0] = nl0; nu4[i0] = nu0;
        nl4[i1] = nl1; nu4[i1] = nu1;
    } else if (i0 < n4) {
        const float4 lv0 = l4[i0], uv0 = u4[i0];
        float4 nl0, nu0;
        do4(lv0, uv0, nl0, nu0);
        nl4[i0] = nl0; nu4[i0] = nu0;
    }
}

// scalar tail (n not divisible by 4)
__global__ void __launch_bounds__(256)
spu_pointwise_tail(const float* __restrict__ l,
                   const float* __restrict__ u,
                   float* __restrict__ nl,
                   float* __restrict__ nu,
                   int start, int n) {
    int i = start + blockIdx.x * blockDim.x + threadIdx.x;
    if (i >= n) return;
    spu_bounds(l[i], u[i], nl[i], nu[i]);
}

extern "C" void kernel_launch(void* const* d_in, const int* in_sizes, int n_in,
                              void* d_out, int out_size) {
    const float* l = (const float*)d_in[0];
    const float* u = (const float*)d_in[1];
    float* out = (float*)d_out;
    const int n = in_sizes[0];
    float* nl = out;
    float* nu = out + n;

    const int n4 = n >> 2;
    if (n4 > 0) {
        const int blocks = (n4 + 511) / 512;          // 512 float4 per block
        spu_pointwise_kernel<<<blocks, 256>>>(
            (const float4*)l, (const float4*)u,
            (float4*)nl, (float4*)nu, n4);
    }
    const int rem_start = n4 << 2;
    if (rem_start < n) {
        const int rem = n - rem_start;
        spu_pointwise_tail<<<(rem + 255) / 256, 256>>>(l, u, nl, nu, rem_start, n);
    }
}

// round 10
// speedup vs baseline: 2.2857x; 1.0134x over previous
#include <cuda_runtime.h>
#include <math.h>

// SPUPointwise — R10. R9 post-mortem: the 8-elems/thread unroll (R7 change 3)
// raised regs 32->45, dropped achieved occupancy 82.5%->51.0%, and cancelled
// the instruction-count wins of the shared-rcp sigmoid + collapsed upper merge
// (net neutral 14.6->14.5us). Each thread already had 4 independent chains via
// the float4 lanes, so the extra unroll added register pressure, not ILP.
// This round: revert to 1 float4/thread (R6 geometry, regs ~32, occ ~83%)
// while KEEPING the slimmer math:
//  * one rcp over the product of 3 sigmoid denominators (all >=1, no overflow)
//  * upper merge: uw/ub = neg ? tangent : (su>sl ? chord : (0,sl))
//
// Output layout: out[0..N) = nl, out[N..2N) = nu.

__device__ __forceinline__ float rcpa(float x) {
    float r; asm("rcp.approx.ftz.f32 %0, %1;" : "=f"(r) : "f"(x)); return r;
}
__device__ __forceinline__ float ex2a(float x) {
    float r; asm("ex2.approx.ftz.f32 %0, %1;" : "=f"(r) : "f"(x)); return r;
}

__device__ __forceinline__ void spu_bounds(float l, float u, float& nl, float& nu) {
    const float NLOG2E = -1.44269504088896340736f;

    const float lpu = l + u;
    const float mid = 0.5f * lpu;

    // three sigmoids with ONE rcp: s_x = 1/(1+e^{-x})
    const float dl = 1.0f + ex2a(NLOG2E * l);
    const float du = 1.0f + ex2a(NLOG2E * u);
    const float dm = 1.0f + ex2a(NLOG2E * mid);
    const float dlu = dl * du;
    const float r3  = rcpa(dlu * dm);
    const float s_l = (du * dm) * r3;
    const float s_u = (dl * dm) * r3;
    const float s_m = dlu * r3;

    // spu at endpoints
    const float sl = (l < 0.0f) ? -s_l : fmaf(l, l, -0.5f);
    const float su = (u < 0.0f) ? -s_u : fmaf(u, u, -0.5f);

    // chord (l,sl)-(u,su)
    const float a_lu = (su - sl) * rcpa(u - l + 1e-8f);
    const float b_lu = fmaf(-l, a_lu, sl);

    // tangent at mid, negative branch: grad = s^2 - s, spu = -s
    const float a_tn = fmaf(s_m, s_m, -s_m);
    const float b_tn = fmaf(-a_tn, mid, -s_m);
    // tangent at mid, positive branch: grad = 2*mid, b = -(mid^2+0.5)
    const float a_tp = lpu;
    const float b_tp = fmaf(-mid, mid, -0.5f);

    // ---- mixed-class lower candidates ----
    // c1: chord (l,sl)-(0,-0.5)
    const float a1 = (-0.5f - sl) * rcpa(1e-8f - l);
    const float b1 = fmaf(-l, a1, sl);
    // first-argmax of q_i = a_i*(l+u)+2*b_i  (== first-argmin of area proxy)
    const float q1 = fmaf(a1, lpu, b1 + b1);
    const bool  tu = (su > sl);   // "normal"; also always true for pos class
    const float q2 = tu ? fmaf(u, fmaf(0.5f, u, l), -1.0f) : -INFINITY;

    const bool c1 = (q1 > -1.0f);                 // q0 = -1
    float lw_m = c1 ? a1 : 0.0f;
    float lb_m = c1 ? b1 : -0.5f;
    const bool c2 = (q2 > fmaxf(q1, -1.0f));
    lw_m = c2 ? u : lw_m;
    lb_m = c2 ? fmaf(-0.25f * u, u, -0.5f) : lb_m;

    // ---- class merge ----
    const bool neg = (u < 0.0f);
    const bool pos = (!neg) && (l > 0.0f);

    const float lw = neg ? a_lu : (pos ? a_tp : lw_m);
    const float lb = neg ? b_lu : (pos ? b_tp : lb_m);
    const float uw = neg ? a_tn : (tu ? a_lu : 0.0f);
    const float ub = neg ? b_tn : (tu ? b_lu : sl);

    // backsubstitution against constant bounds
    nl = fmaf(lw, (lw > 0.0f) ? l : u, lb);
    nu = fmaf(uw, (uw > 0.0f) ? u : l, ub);
}

__global__ void __launch_bounds__(256)
spu_pointwise_kernel(const float4* __restrict__ l4,
                     const float4* __restrict__ u4,
                     float4* __restrict__ nl4,
                     float4* __restrict__ nu4,
                     int n4) {
    int i = blockIdx.x * blockDim.x + threadIdx.x;
    if (i >= n4) return;

    const float4 lv = l4[i];
    const float4 uv = u4[i];
    float4 nlv, nuv;
    spu_bounds(lv.x, uv.x, nlv.x, nuv.x);
    spu_bounds(lv.y, uv.y, nlv.y, nuv.y);
    spu_bounds(lv.z, uv.z, nlv.z, nuv.z);
    spu_bounds(lv.w, uv.w, nlv.w, nuv.w);
    nl4[i] = nlv;
    nu4[i] = nuv;
}

// scalar tail (n not divisible by 4)
__global__ void __launch_bounds__(256)
spu_pointwise_tail(const float* __restrict__ l,
                   const float* __restrict__ u,
                   float* __restrict__ nl,
                   float* __restrict__ nu,
                   int start, int n) {
    int i = start + blockIdx.x * blockDim.x + threadIdx.x;
    if (i >= n) return;
    spu_bounds(l[i], u[i], nl[i], nu[i]);
}

extern "C" void kernel_launch(void* const* d_in, const int* in_sizes, int n_in,
                              void* d_out, int out_size) {
    const float* l = (const float*)d_in[0];
    const float* u = (const float*)d_in[1];
    float* out = (float*)d_out;
    const int n = in_sizes[0];
    float* nl = out;
    float* nu = out + n;

    const int n4 = n >> 2;
    if (n4 > 0) {
        const int threads = 256;
        const int blocks = (n4 + threads - 1) / threads;
        spu_pointwise_kernel<<<blocks, threads>>>(
            (const float4*)l, (const float4*)u,
            (float4*)nl, (float4*)nu, n4);
    }
    const int rem_start = n4 << 2;
    if (rem_start < n) {
        const int rem = n - rem_start;
        spu_pointwise_tail<<<(rem + 255) / 256, 256>>>(l, u, nl, nu, rem_start, n);
    }
}

// round 11
// speedup vs baseline: 2.3432x; 1.0252x over previous
#include <cuda_runtime.h>
#include <math.h>

// SPUPointwise — R11. Key simplification: everywhere the reference
// backsubstitutes the chord (l,sl)-(u,su), the selected evaluation point is u
// (chord slope sign is determined by class: spu decreasing on x<0, increasing
// on x>0), and chord(u) == su up to the 1e-8 denominator shift (error <=
// 0.25*1e-8 absolute). So the chord (a_lu,b_lu: 1 rcp + ~5 fma + merge
// selects) is eliminated entirely:
//   neg lower  -> su      pos upper  -> su
//   mixed upper-> su>sl ? su : sl
// Remaining classes evaluate their final nl/nu candidate directly (tangent
// signs also statically known), and we select among scalar candidates instead
// of merging (w,b) pairs. Mixed-case argmin tie-break structure kept identical
// to prior passing rounds (b1-route for q1/nl1).
// ~50 instrs/elem vs ~88 in R10.
//
// Output layout: out[0..N) = nl, out[N..2N) = nu.

__device__ __forceinline__ float rcpa(float x) {
    float r; asm("rcp.approx.ftz.f32 %0, %1;" : "=f"(r) : "f"(x)); return r;
}
__device__ __forceinline__ float ex2a(float x) {
    float r; asm("ex2.approx.ftz.f32 %0, %1;" : "=f"(r) : "f"(x)); return r;
}

__device__ __forceinline__ void spu_bounds(float l, float u, float& nl, float& nu) {
    const float NLOG2E = -1.44269504088896340736f;

    const float lpu = l + u;
    const float mid = 0.5f * lpu;

    // three sigmoids with ONE rcp: s_x = 1/(1+e^{-x})
    const float dl = 1.0f + ex2a(NLOG2E * l);
    const float du = 1.0f + ex2a(NLOG2E * u);
    const float dm = 1.0f + ex2a(NLOG2E * mid);
    const float dlu = dl * du;
    const float r3  = rcpa(dlu * dm);
    const float s_l = (du * dm) * r3;
    const float s_u = (dl * dm) * r3;
    const float s_m = dlu * r3;

    // spu at endpoints
    const float sl = (l < 0.0f) ? -s_l : fmaf(l, l, -0.5f);
    const float su = (u < 0.0f) ? -s_u : fmaf(u, u, -0.5f);

    // ---- neg class upper: tangent at mid (mid<0), slope a_tn<0 -> eval at l
    const float a_tn = fmaf(s_m, s_m, -s_m);          // s^2 - s
    const float b_tn = fmaf(-a_tn, mid, -s_m);
    const float nu_neg = fmaf(a_tn, l, b_tn);

    // ---- pos class lower: tangent at mid (mid>0), slope lpu>0 -> eval at l
    const float b_tp = fmaf(-mid, mid, -0.5f);
    const float nl_pos = fmaf(lpu, l, b_tp);

    // ---- mixed class lower candidates (a1<=0 -> eval at u; c2 slope u>0 -> at l)
    const float a1 = (-0.5f - sl) * rcpa(1e-8f - l);
    const float b1 = fmaf(-l, a1, sl);
    const float nl1 = fmaf(a1, u, b1);
    const float q1  = fmaf(a1, lpu, b1 + b1);
    const bool  tu  = (su > sl);                       // "normal" (true for pos)
    const float q2  = tu ? fmaf(u, fmaf(0.5f, u, l), -1.0f) : -INFINITY;
    const float nl2 = fmaf(u, fmaf(-0.25f, u, l), -0.5f);  // u*l - u^2/4 - 0.5

    float nl_m = (q1 > -1.0f) ? nl1 : -0.5f;           // q0 = -1, c0 -> -0.5
    nl_m = (q2 > fmaxf(q1, -1.0f)) ? nl2 : nl_m;

    // ---- class merge (neg => l<0 => !lgt0, so nesting is safe) ----
    const bool neg  = (u < 0.0f);
    const bool lgt0 = (l > 0.0f);

    nl = neg ? su     : (lgt0 ? nl_pos : nl_m);
    nu = neg ? nu_neg : (tu ? su : sl);
}

__global__ void __launch_bounds__(256)
spu_pointwise_kernel(const float4* __restrict__ l4,
                     const float4* __restrict__ u4,
                     float4* __restrict__ nl4,
                     float4* __restrict__ nu4,
                     int n4) {
    int i = blockIdx.x * blockDim.x + threadIdx.x;
    if (i >= n4) return;

    const float4 lv = l4[i];
    const float4 uv = u4[i];
    float4 nlv, nuv;
    spu_bounds(lv.x, uv.x, nlv.x, nuv.x);
    spu_bounds(lv.y, uv.y, nlv.y, nuv.y);
    spu_bounds(lv.z, uv.z, nlv.z, nuv.z);
    spu_bounds(lv.w, uv.w, nlv.w, nuv.w);
    nl4[i] = nlv;
    nu4[i] = nuv;
}

// scalar tail (n not divisible by 4)
__global__ void __launch_bounds__(256)
spu_pointwise_tail(const float* __restrict__ l,
                   const float* __restrict__ u,
                   float* __restrict__ nl,
                   float* __restrict__ nu,
                   int start, int n) {
    int i = start + blockIdx.x * blockDim.x + threadIdx.x;
    if (i >= n) return;
    spu_bounds(l[i], u[i], nl[i], nu[i]);
}

extern "C" void kernel_launch(void* const* d_in, const int* in_sizes, int n_in,
                              void* d_out, int out_size) {
    const float* l = (const float*)d_in[0];
    const float* u = (const float*)d_in[1];
    float* out = (float*)d_out;
    const int n = in_sizes[0];
    float* nl = out;
    float* nu = out + n;

    const int n4 = n >> 2;
    if (n4 > 0) {
        const int threads = 256;
        const int blocks = (n4 + threads - 1) / threads;
        spu_pointwise_kernel<<<blocks, threads>>>(
            (const float4*)l, (const float4*)u,
            (float4*)nl, (float4*)nu, n4);
    }
    const int rem_start = n4 << 2;
    if (rem_start < n) {
        const int rem = n - rem_start;
        spu_pointwise_tail<<<(rem + 255) / 256, 256>>>(l, u, nl, nu, rem_start, n);
    }
}

// round 12
// speedup vs baseline: 2.4498x; 1.0455x over previous
#include <cuda_runtime.h>
#include <math.h>

// SPUPointwise — R12. R11's chord elimination was a real win (kernel 14.4 ->
// 13.0us, alu 31 -> 23.5%) but regs crept 32 -> 34, crossing an allocation
// granularity boundary (34 -> 40 alloc -> 6 blocks/SM instead of 8), dropping
// achieved occupancy 81.3% -> 61.8% and eating part of the win via lost
// latency hiding. This round's single change: __launch_bounds__(256, 8)
// forces regs <= 32 (256 thr x 8 blk = 2048 thr/SM), restoring full
// occupancy. Math is byte-identical to R11 (passed, rel_err 7.4e-8):
//  * chord fully eliminated (chord eval point is always u -> value su)
//  * one rcp for all 3 sigmoids; direct per-class nl/nu candidates
//
// Output layout: out[0..N) = nl, out[N..2N) = nu.

__device__ __forceinline__ float rcpa(float x) {
    float r; asm("rcp.approx.ftz.f32 %0, %1;" : "=f"(r) : "f"(x)); return r;
}
__device__ __forceinline__ float ex2a(float x) {
    float r; asm("ex2.approx.ftz.f32 %0, %1;" : "=f"(r) : "f"(x)); return r;
}

__device__ __forceinline__ void spu_bounds(float l, float u, float& nl, float& nu) {
    const float NLOG2E = -1.44269504088896340736f;

    const float lpu = l + u;
    const float mid = 0.5f * lpu;

    // three sigmoids with ONE rcp: s_x = 1/(1+e^{-x})
    const float dl = 1.0f + ex2a(NLOG2E * l);
    const float du = 1.0f + ex2a(NLOG2E * u);
    const float dm = 1.0f + ex2a(NLOG2E * mid);
    const float dlu = dl * du;
    const float r3  = rcpa(dlu * dm);
    const float s_l = (du * dm) * r3;
    const float s_u = (dl * dm) * r3;
    const float s_m = dlu * r3;

    // spu at endpoints
    const float sl = (l < 0.0f) ? -s_l : fmaf(l, l, -0.5f);
    const float su = (u < 0.0f) ? -s_u : fmaf(u, u, -0.5f);

    // ---- neg class upper: tangent at mid (mid<0), slope a_tn<0 -> eval at l
    const float a_tn = fmaf(s_m, s_m, -s_m);          // s^2 - s
    const float b_tn = fmaf(-a_tn, mid, -s_m);
    const float nu_neg = fmaf(a_tn, l, b_tn);

    // ---- pos class lower: tangent at mid (mid>0), slope lpu>0 -> eval at l
    const float b_tp = fmaf(-mid, mid, -0.5f);
    const float nl_pos = fmaf(lpu, l, b_tp);

    // ---- mixed class lower candidates (a1<=0 -> eval at u; c2 slope u>0 -> at l)
    const float a1 = (-0.5f - sl) * rcpa(1e-8f - l);
    const float b1 = fmaf(-l, a1, sl);
    const float nl1 = fmaf(a1, u, b1);
    const float q1  = fmaf(a1, lpu, b1 + b1);
    const bool  tu  = (su > sl);                       // "normal" (true for pos)
    const float q2  = tu ? fmaf(u, fmaf(0.5f, u, l), -1.0f) : -INFINITY;
    const float nl2 = fmaf(u, fmaf(-0.25f, u, l), -0.5f);  // u*l - u^2/4 - 0.5

    float nl_m = (q1 > -1.0f) ? nl1 : -0.5f;           // q0 = -1, c0 -> -0.5
    nl_m = (q2 > fmaxf(q1, -1.0f)) ? nl2 : nl_m;

    // ---- class merge (neg => l<0 => !lgt0, so nesting is safe) ----
    const bool neg  = (u < 0.0f);
    const bool lgt0 = (l > 0.0f);

    nl = neg ? su     : (lgt0 ? nl_pos : nl_m);
    nu = neg ? nu_neg : (tu ? su : sl);
}

__global__ void __launch_bounds__(256, 8)
spu_pointwise_kernel(const float4* __restrict__ l4,
                     const float4* __restrict__ u4,
                     float4* __restrict__ nl4,
                     float4* __restrict__ nu4,
                     int n4) {
    int i = blockIdx.x * blockDim.x + threadIdx.x;
    if (i >= n4) return;

    const float4 lv = l4[i];
    const float4 uv = u4[i];
    float4 nlv, nuv;
    spu_bounds(lv.x, uv.x, nlv.x, nuv.x);
    spu_bounds(lv.y, uv.y, nlv.y, nuv.y);
    spu_bounds(lv.z, uv.z, nlv.z, nuv.z);
    spu_bounds(lv.w, uv.w, nlv.w, nuv.w);
    nl4[i] = nlv;
    nu4[i] = nuv;
}

// scalar tail (n not divisible by 4)
__global__ void __launch_bounds__(256, 8)
spu_pointwise_tail(const float* __restrict__ l,
                   const float* __restrict__ u,
                   float* __restrict__ nl,
                   float* __restrict__ nu,
                   int start, int n) {
    int i = start + blockIdx.x * blockDim.x + threadIdx.x;
    if (i >= n) return;
    spu_bounds(l[i], u[i], nl[i], nu[i]);
}

extern "C" void kernel_launch(void* const* d_in, const int* in_sizes, int n_in,
                              void* d_out, int out_size) {
    const float* l = (const float*)d_in[0];
    const float* u = (const float*)d_in[1];
    float* out = (float*)d_out;
    const int n = in_sizes[0];
    float* nl = out;
    float* nu = out + n;

    const int n4 = n >> 2;
    if (n4 > 0) {
        const int threads = 256;
        const int blocks = (n4 + threads - 1) / threads;
        spu_pointwise_kernel<<<blocks, threads>>>(
            (const float4*)l, (const float4*)u,
            (float4*)nl, (float4*)nu, n4);
    }
    const int rem_start = n4 << 2;
    if (rem_start < n) {
        const int rem = n - rem_start;
        spu_pointwise_tail<<<(rem + 255) / 256, 256>>>(l, u, nl, nu, rem_start, n);
    }
}

// round 13
// speedup vs baseline: 2.5409x; 1.0372x over previous
#include <cuda_runtime.h>
#include <math.h>

// SPUPointwise — R13. R12 evidence: occ 62%->80% bought only 1.5% => purely
// instruction-throughput bound; only issue-slot cuts matter. This round:
// sigmoid demand analysis — per class only these are consumed:
//   neg (u<0):   s_u (nl=su) and s_m (tangent); sl is DEAD
//   mixed(l<=0): s_l only (su=u^2-0.5 since u>=0; s_m dead)
//   pos:         none
// => TWO sigmoids suffice: s1 = sigmoid(neg ? u : l), s2 = sigmoid(mid),
// with sl garbage-but-unused in neg (verified: nl, nu, tu/q2 all dead there).
// MUFU 5->4/elem, ~6 fewer fma/alu ops. Also non-neg upper select
// (tu ? su : sl) == fmaxf(su, sl) exactly -> FMNMX replaces SETP+SEL.
//
// Output layout: out[0..N) = nl, out[N..2N) = nu.

__device__ __forceinline__ float rcpa(float x) {
    float r; asm("rcp.approx.ftz.f32 %0, %1;" : "=f"(r) : "f"(x)); return r;
}
__device__ __forceinline__ float ex2a(float x) {
    float r; asm("ex2.approx.ftz.f32 %0, %1;" : "=f"(r) : "f"(x)); return r;
}

__device__ __forceinline__ void spu_bounds(float l, float u, float& nl, float& nu) {
    const float NLOG2E = -1.44269504088896340736f;

    const float lpu = l + u;
    const float mid = 0.5f * lpu;

    const bool neg  = (u < 0.0f);
    const bool lgt0 = (l > 0.0f);

    // two sigmoids, one shared rcp: s1 = sigmoid(neg ? u : l), s2 = sigmoid(mid)
    const float x1 = neg ? u : l;
    const float e1 = ex2a(NLOG2E * x1);
    const float e2 = ex2a(NLOG2E * mid);
    const float d1 = 1.0f + e1;
    const float d2 = 1.0f + e2;
    const float r  = rcpa(d1 * d2);
    const float s1 = d2 * r;   // sigmoid(x1)
    const float s2 = d1 * r;   // sigmoid(mid)

    // spu endpoints (sl is garbage in neg class — dead there)
    const float sl = (l < 0.0f) ? -s1 : fmaf(l, l, -0.5f);
    const float su = neg ? -s1 : fmaf(u, u, -0.5f);

    // neg upper: tangent at mid (grad = s^2-s, spu = -s), evaluated at l
    const float a_tn = fmaf(s2, s2, -s2);
    const float b_tn = fmaf(-a_tn, mid, -s2);
    const float nu_neg = fmaf(a_tn, l, b_tn);

    // pos lower: tangent at mid (quadratic branch), evaluated at l
    const float nl_pos = fmaf(lpu, l, fmaf(-mid, mid, -0.5f));

    // mixed lower candidates (a1<=0 -> eval at u; c2 slope u>0 -> eval at l)
    const float a1 = (-0.5f - sl) * rcpa(1e-8f - l);
    const float b1 = fmaf(-l, a1, sl);
    const float nl1 = fmaf(a1, u, b1);
    const float q1  = fmaf(a1, lpu, b1 + b1);
    const bool  tu  = (su > sl);                       // "normal"
    const float q2  = tu ? fmaf(u, fmaf(0.5f, u, l), -1.0f) : -INFINITY;
    const float nl2 = fmaf(u, fmaf(-0.25f, u, l), -0.5f);  // u*l - u^2/4 - 0.5

    float nl_m = (q1 > -1.0f) ? nl1 : -0.5f;           // q0 = -1 -> c0 gives -0.5
    nl_m = (q2 > fmaxf(q1, -1.0f)) ? nl2 : nl_m;

    // class merge (neg => l<0 => !lgt0, nesting safe)
    nl = neg ? su : (lgt0 ? nl_pos : nl_m);
    nu = neg ? nu_neg : fmaxf(su, sl);                 // == tu ? su : sl
}

__global__ void __launch_bounds__(256, 8)
spu_pointwise_kernel(const float4* __restrict__ l4,
                     const float4* __restrict__ u4,
                     float4* __restrict__ nl4,
                     float4* __restrict__ nu4,
                     int n4) {
    int i = blockIdx.x * blockDim.x + threadIdx.x;
    if (i >= n4) return;

    const float4 lv = l4[i];
    const float4 uv = u4[i];
    float4 nlv, nuv;
    spu_bounds(lv.x, uv.x, nlv.x, nuv.x);
    spu_bounds(lv.y, uv.y, nlv.y, nuv.y);
    spu_bounds(lv.z, uv.z, nlv.z, nuv.z);
    spu_bounds(lv.w, uv.w, nlv.w, nuv.w);
    nl4[i] = nlv;
    nu4[i] = nuv;
}

// scalar tail (n not divisible by 4)
__global__ void __launch_bounds__(256, 8)
spu_pointwise_tail(const float* __restrict__ l,
                   const float* __restrict__ u,
                   float* __restrict__ nl,
                   float* __restrict__ nu,
                   int start, int n) {
    int i = start + blockIdx.x * blockDim.x + threadIdx.x;
    if (i >= n) return;
    spu_bounds(l[i], u[i], nl[i], nu[i]);
}

extern "C" void kernel_launch(void* const* d_in, const int* in_sizes, int n_in,
                              void* d_out, int out_size) {
    const float* l = (const float*)d_in[0];
    const float* u = (const float*)d_in[1];
    float* out = (float*)d_out;
    const int n = in_sizes[0];
    float* nl = out;
    float* nu = out + n;

    const int n4 = n >> 2;
    if (n4 > 0) {
        const int threads = 256;
        const int blocks = (n4 + threads - 1) / threads;
        spu_pointwise_kernel<<<blocks, threads>>>(
            (const float4*)l, (const float4*)u,
            (float4*)nl, (float4*)nu, n4);
    }
    const int rem_start = n4 << 2;
    if (rem_start < n) {
        const int rem = n - rem_start;
        spu_pointwise_tail<<<(rem + 255) / 256, 256>>>(l, u, nl, nu, rem_start, n);
    }
}

// round 15
// speedup vs baseline: 2.6667x; 1.0495x over previous
#include <cuda_runtime.h>
#include <math.h>

// SPUPointwise — R15 (resubmit of R14; round 14 died on "GB300 container
// failed twice" before compile/run — same infra flake as rounds 4/5/7/8,
// each resolved by unchanged resubmission). Theory unchanged:
// R13 showed the timed loop is L2-warm (64MiB fits L2) and still
// instruction-bound, while ncu's cold-cache replay sits at a DRAM floor.
// This round: select/dead-value surgery.
//  * su select gone: every consumer of su has u>=0 -> unconditional
//    suq = u^2-0.5; neg-class nl takes -s1 directly.
//  * q2 -INFINITY select gone: c2 = tu && (q2p>q1) && (q2p>-1)
//    == (q2 > max(q1,q0)) under the tu gate, strictness preserved.
//  * fmaxf(q1,-1) folded into the compares.
//
// Output layout: out[0..N) = nl, out[N..2N) = nu.

__device__ __forceinline__ float rcpa(float x) {
    float r; asm("rcp.approx.ftz.f32 %0, %1;" : "=f"(r) : "f"(x)); return r;
}
__device__ __forceinline__ float ex2a(float x) {
    float r; asm("ex2.approx.ftz.f32 %0, %1;" : "=f"(r) : "f"(x)); return r;
}

__device__ __forceinline__ void spu_bounds(float l, float u, float& nl, float& nu) {
    const float NLOG2E = -1.44269504088896340736f;

    const float lpu = l + u;
    const float mid = 0.5f * lpu;

    const bool neg  = (u < 0.0f);
    const bool lgt0 = (l > 0.0f);

    // two sigmoids, one shared rcp: s1 = sigmoid(neg ? u : l), s2 = sigmoid(mid)
    const float x1 = neg ? u : l;
    const float e1 = ex2a(NLOG2E * x1);
    const float e2 = ex2a(NLOG2E * mid);
    const float d1 = 1.0f + e1;
    const float d2 = 1.0f + e2;
    const float r  = rcpa(d1 * d2);
    const float s1 = d2 * r;   // sigmoid(x1)
    const float s2 = d1 * r;   // sigmoid(mid)

    // endpoints: suq valid wherever su is consumed (u>=0 there); sl garbage in
    // neg class but dead there.
    const float suq = fmaf(u, u, -0.5f);
    const float sl  = (l < 0.0f) ? -s1 : fmaf(l, l, -0.5f);

    // neg upper: tangent at mid (grad = s^2-s, spu = -s), evaluated at l
    const float a_tn = fmaf(s2, s2, -s2);
    const float b_tn = fmaf(-a_tn, mid, -s2);
    const float nu_neg = fmaf(a_tn, l, b_tn);

    // pos lower: tangent at mid (quadratic branch), evaluated at l
    const float nl_pos = fmaf(lpu, l, fmaf(-mid, mid, -0.5f));

    // mixed lower candidates (a1<=0 -> eval at u; c2 slope u>0 -> eval at l)
    const float a1  = (-0.5f - sl) * rcpa(1e-8f - l);
    const float b1  = fmaf(-l, a1, sl);
    const float nl1 = fmaf(a1, u, b1);
    const float q1  = fmaf(a1, lpu, b1 + b1);
    const float q2p = fmaf(u, fmaf(0.5f, u, l), -1.0f);
    const float nl2 = fmaf(u, fmaf(-0.25f, u, l), -0.5f);  // u*l - u^2/4 - 0.5

    const bool tu = (suq > sl);                        // "normal"
    const bool c1 = (q1 > -1.0f);
    const bool c2 = tu && (q2p > q1) && (q2p > -1.0f); // q2 > max(q1, q0)

    const float nl_m = c2 ? nl2 : (c1 ? nl1 : -0.5f);

    // class merge (neg => l<0 => !lgt0, nesting safe)
    nl = neg ? -s1    : (lgt0 ? nl_pos : nl_m);
    nu = neg ? nu_neg : fmaxf(suq, sl);                // == tu ? su : sl
}

__global__ void __launch_bounds__(256, 8)
spu_pointwise_kernel(const float4* __restrict__ l4,
                     const float4* __restrict__ u4,
                     float4* __restrict__ nl4,
                     float4* __restrict__ nu4,
                     int n4) {
    int i = blockIdx.x * blockDim.x + threadIdx.x;
    if (i >= n4) return;

    const float4 lv = l4[i];
    const float4 uv = u4[i];
    float4 nlv, nuv;
    spu_bounds(lv.x, uv.x, nlv.x, nuv.x);
    spu_bounds(lv.y, uv.y, nlv.y, nuv.y);
    spu_bounds(lv.z, uv.z, nlv.z, nuv.z);
    spu_bounds(lv.w, uv.w, nlv.w, nuv.w);
    nl4[i] = nlv;
    nu4[i] = nuv;
}

// scalar tail (n not divisible by 4)
__global__ void __launch_bounds__(256, 8)
spu_pointwise_tail(const float* __restrict__ l,
                   const float* __restrict__ u,
                   float* __restrict__ nl,
                   float* __restrict__ nu,
                   int start, int n) {
    int i = start + blockIdx.x * blockDim.x + threadIdx.x;
    if (i >= n) return;
    spu_bounds(l[i], u[i], nl[i], nu[i]);
}

extern "C" void kernel_launch(void* const* d_in, const int* in_sizes, int n_in,
                              void* d_out, int out_size) {
    const float* l = (const float*)d_in[0];
    const float* u = (const float*)d_in[1];
    float* out = (float*)d_out;
    const int n = in_sizes[0];
    float* nl = out;
    float* nu = out + n;

    const int n4 = n >> 2;
    if (n4 > 0) {
        const int threads = 256;
        const int blocks = (n4 + threads - 1) / threads;
        spu_pointwise_kernel<<<blocks, threads>>>(
            (const float4*)l, (const float4*)u,
            (float4*)nl, (float4*)nu, n4);
    }
    const int rem_start = n4 << 2;
    if (rem_start < n) {
        const int rem = n - rem_start;
        spu_pointwise_tail<<<(rem + 255) / 256, 256>>>(l, u, nl, nu, rem_start, n);
    }
}